// round 1
// baseline (speedup 1.0000x reference)
#include <cuda_runtime.h>
#include <math.h>

// Problem constants
#define BB 4
#define TT 2048
#define CC 512
#define HH 8
#define HD 64
#define MM (BB*TT)          // 8192
#define BH (BB*HH)          // 32

// ---------------- device scratch (no runtime allocation allowed) ----------------
__device__ float g_qkv[MM * 3 * CC];      // 8192 x 1536
__device__ float g_q[BH * TT * HD];       // [bh][t][d]
__device__ float g_k[BH * TT * HD];
__device__ float g_v[BH * TT * HD];
__device__ float g_att[MM * CC];          // [b*T+t][h*64+d]

// =====================================================================
// SGEMM: C[M,N] = A[M,K] @ W[N,K]^T   (fp32, 128x128 block, 8x8/thread)
// M,N multiples of 128; K multiple of 8. Row-major A, W, C.
// =====================================================================
__global__ void __launch_bounds__(256) sgemm_nt(const float* __restrict__ A,
                                                const float* __restrict__ W,
                                                float* __restrict__ Cmat,
                                                int M, int N, int K) {
    __shared__ float As[8][132];   // pad 132 (%4==0 for float4, kills store conflicts)
    __shared__ float Bs[8][132];

    const int tid = threadIdx.x;
    const int bm = blockIdx.y * 128;
    const int bn = blockIdx.x * 128;
    const int tr = tid >> 4;          // 0..15
    const int tc = tid & 15;          // 0..15
    const int lrow = tid >> 1;        // 0..127
    const int lcol = (tid & 1) * 4;   // 0 or 4

    const float* Ap = A + (size_t)(bm + lrow) * K + lcol;
    const float* Wp = W + (size_t)(bn + lrow) * K + lcol;

    float acc[8][8];
#pragma unroll
    for (int i = 0; i < 8; i++)
#pragma unroll
        for (int j = 0; j < 8; j++) acc[i][j] = 0.f;

    for (int k0 = 0; k0 < K; k0 += 8) {
        float4 a4 = *(const float4*)(Ap + k0);
        float4 b4 = *(const float4*)(Wp + k0);
        __syncthreads();   // prior iteration's compute done before overwrite
        As[lcol + 0][lrow] = a4.x; As[lcol + 1][lrow] = a4.y;
        As[lcol + 2][lrow] = a4.z; As[lcol + 3][lrow] = a4.w;
        Bs[lcol + 0][lrow] = b4.x; Bs[lcol + 1][lrow] = b4.y;
        Bs[lcol + 2][lrow] = b4.z; Bs[lcol + 3][lrow] = b4.w;
        __syncthreads();
#pragma unroll
        for (int kk = 0; kk < 8; kk++) {
            float ra[8], rb[8];
            *(float4*)(ra)     = *(const float4*)&As[kk][tr * 8];
            *(float4*)(ra + 4) = *(const float4*)&As[kk][tr * 8 + 4];
            *(float4*)(rb)     = *(const float4*)&Bs[kk][tc * 8];
            *(float4*)(rb + 4) = *(const float4*)&Bs[kk][tc * 8 + 4];
#pragma unroll
            for (int i = 0; i < 8; i++)
#pragma unroll
                for (int j = 0; j < 8; j++)
                    acc[i][j] += ra[i] * rb[j];
        }
    }

#pragma unroll
    for (int i = 0; i < 8; i++) {
        float* crow = Cmat + (size_t)(bm + tr * 8 + i) * N + bn + tc * 8;
#pragma unroll
        for (int j = 0; j < 8; j++) crow[j] = acc[i][j];
    }
}

// =====================================================================
// RoPE + split qkv[8192][1536] -> g_q/g_k/g_v in [bh][t][d] layout.
// One thread per (bh, t, d<32) pair.
// =====================================================================
__global__ void __launch_bounds__(256) rope_split(const float* __restrict__ qkv,
                                                  const float* __restrict__ cosp,
                                                  const float* __restrict__ sinp,
                                                  float* __restrict__ q,
                                                  float* __restrict__ k,
                                                  float* __restrict__ v) {
    int idx = blockIdx.x * blockDim.x + threadIdx.x;   // 32*2048*32
    int d  = idx & 31;
    int t  = (idx >> 5) & (TT - 1);
    int bh = idx >> 16;                                // /(32*2048)
    int b = bh >> 3, h = bh & 7;

    size_t rowq = (size_t)(b * TT + t) * (3 * CC);
    int c = h * HD + d;
    float c1 = cosp[t * HD + d],      s1 = sinp[t * HD + d];
    float c2 = cosp[t * HD + d + 32], s2 = sinp[t * HD + d + 32];
    size_t dst = (size_t)(bh * TT + t) * HD + d;

    float x1 = qkv[rowq + c];
    float x2 = qkv[rowq + c + 32];
    q[dst]      = x1 * c1 - x2 * s1;
    q[dst + 32] = x2 * c2 + x1 * s2;

    x1 = qkv[rowq + CC + c];
    x2 = qkv[rowq + CC + c + 32];
    k[dst]      = x1 * c1 - x2 * s1;
    k[dst + 32] = x2 * c2 + x1 * s2;

    v[dst]      = qkv[rowq + 2 * CC + c];
    v[dst + 32] = qkv[rowq + 2 * CC + c + 32];
}

// =====================================================================
// Flash attention (causal), fp32. Block = 64 q-rows x (bh), 256 threads.
// Thread (r = tid/4, quad = tid%4): 8 score cols / 16 out cols, stride-4.
// K-tile = 32. Online softmax, O accumulated in registers.
// =====================================================================
__global__ void __launch_bounds__(256) attn_kernel(const float* __restrict__ Q,
                                                   const float* __restrict__ K,
                                                   const float* __restrict__ V,
                                                   float* __restrict__ Oatt) {
    __shared__ float Qs[64][68];
    __shared__ float Ks[32][68];
    __shared__ float Vs[32][68];
    __shared__ float Ps[64][36];

    const int tid  = threadIdx.x;
    const int q0   = blockIdx.x * 64;
    const int bh   = blockIdx.y;
    const int r    = tid >> 2;     // 0..63
    const int quad = tid & 3;      // 0..3
    const int qglob = q0 + r;

    // load Q tile (64x64)
    const float* qb = Q + (size_t)(bh * TT + q0) * HD;
#pragma unroll
    for (int i = 0; i < 4; i++) {
        int idx4 = tid + i * 256;
        int row = idx4 >> 4, col = (idx4 & 15) * 4;
        *(float4*)&Qs[row][col] = *(const float4*)(qb + row * HD + col);
    }

    float m = -1e30f, l = 0.f;
    float acc[16];
#pragma unroll
    for (int j = 0; j < 16; j++) acc[j] = 0.f;

    const int nkt = (q0 >> 5) + 2;   // tiles up to and including the diagonal
    for (int kt = 0; kt < nkt; kt++) {
        const int k0 = kt * 32;
        __syncthreads();   // previous AV reads of Ks/Vs done
        {
            const float* kb = K + (size_t)(bh * TT + k0) * HD;
            const float* vb = V + (size_t)(bh * TT + k0) * HD;
#pragma unroll
            for (int i = 0; i < 2; i++) {
                int idx4 = tid + i * 256;
                int row = idx4 >> 4, col = (idx4 & 15) * 4;
                *(float4*)&Ks[row][col] = *(const float4*)(kb + row * HD + col);
                *(float4*)&Vs[row][col] = *(const float4*)(vb + row * HD + col);
            }
        }
        __syncthreads();

        // S = (Q K^T) * 0.125, causal mask
        float s[8];
#pragma unroll
        for (int i = 0; i < 8; i++) s[i] = 0.f;
#pragma unroll 16
        for (int d = 0; d < 64; d++) {
            float qd = Qs[r][d];
#pragma unroll
            for (int i = 0; i < 8; i++) s[i] += qd * Ks[quad + 4 * i][d];
        }

        float tm = -1e30f;
        bool msk[8];
#pragma unroll
        for (int i = 0; i < 8; i++) {
            int kg = k0 + quad + 4 * i;
            msk[i] = (kg <= qglob);
            s[i] = msk[i] ? s[i] * 0.125f : -1e30f;
            tm = fmaxf(tm, s[i]);
        }
        tm = fmaxf(tm, __shfl_xor_sync(0xffffffffu, tm, 1));
        tm = fmaxf(tm, __shfl_xor_sync(0xffffffffu, tm, 2));

        float nm   = fmaxf(m, tm);
        float resc = __expf(m - nm);          // both -1e30 -> exp(0)=1, safe
        float p[8], rs = 0.f;
#pragma unroll
        for (int i = 0; i < 8; i++) {
            p[i] = msk[i] ? __expf(s[i] - nm) : 0.f;
            rs += p[i];
        }
        rs += __shfl_xor_sync(0xffffffffu, rs, 1);
        rs += __shfl_xor_sync(0xffffffffu, rs, 2);
        l = l * resc + rs;
        m = nm;
#pragma unroll
        for (int j = 0; j < 16; j++) acc[j] *= resc;

#pragma unroll
        for (int i = 0; i < 8; i++) Ps[r][quad + 4 * i] = p[i];
        __syncwarp();   // P row r is produced & consumed by the same warp

        // O += P @ V
#pragma unroll 8
        for (int kk = 0; kk < 32; kk++) {
            float pv = Ps[r][kk];
#pragma unroll
            for (int j = 0; j < 16; j++) acc[j] += pv * Vs[kk][quad + 4 * j];
        }
    }

    // write out to [b][t][h*64 + c] layout for the output GEMM
    const int b = bh >> 3, h = bh & 7;
    float inv = 1.f / l;
    float* ob = Oatt + (size_t)(b * TT + qglob) * CC + h * HD;
#pragma unroll
    for (int j = 0; j < 16; j++) ob[quad + 4 * j] = acc[j] * inv;
}

// =====================================================================
extern "C" void kernel_launch(void* const* d_in, const int* in_sizes, int n_in,
                              void* d_out, int out_size) {
    const float* x    = (const float*)d_in[0];
    const float* cosp = (const float*)d_in[1];
    const float* sinp = (const float*)d_in[2];
    const float* Wqkv = (const float*)d_in[3];
    const float* Wout = (const float*)d_in[4];
    float* out = (float*)d_out;

    float *qkv, *q, *k, *v, *att;
    cudaGetSymbolAddress((void**)&qkv, g_qkv);
    cudaGetSymbolAddress((void**)&q,   g_q);
    cudaGetSymbolAddress((void**)&k,   g_k);
    cudaGetSymbolAddress((void**)&v,   g_v);
    cudaGetSymbolAddress((void**)&att, g_att);

    // 1) qkv = x @ Wqkv^T            [8192,512] x [1536,512]^T
    sgemm_nt<<<dim3((3 * CC) / 128, MM / 128), 256>>>(x, Wqkv, qkv, MM, 3 * CC, CC);
    // 2) RoPE + split into head-major q/k/v
    rope_split<<<(BH * TT * 32) / 256, 256>>>(qkv, cosp, sinp, q, k, v);
    // 3) causal flash attention
    attn_kernel<<<dim3(TT / 64, BH), 256>>>(q, k, v, att);
    // 4) out = att @ Wout^T          [8192,512] x [512,512]^T
    sgemm_nt<<<dim3(CC / 128, MM / 128), 256>>>(att, Wout, out, MM, CC, CC);
}

// round 2
// speedup vs baseline: 2.6798x; 2.6798x over previous
#include <cuda_runtime.h>
#include <math.h>

// Problem constants
#define BB 4
#define TT 2048
#define CC 512
#define HH 8
#define HD 64
#define MM (BB*TT)          // 8192
#define BH (BB*HH)          // 32

// ---------------- device scratch (no runtime allocation allowed) ----------------
__device__ float g_qkv[MM * 3 * CC];      // 8192 x 1536
__device__ float g_q[BH * TT * HD];       // [bh][t][d]
__device__ float g_k[BH * TT * HD];
__device__ float g_v[BH * TT * HD];
__device__ float g_att[MM * CC];          // [b*T+t][h*64+d]

// ---------------- tf32 helpers ----------------
__device__ __forceinline__ unsigned f2tf32(float x) {
    unsigned r;
    asm("cvt.rna.tf32.f32 %0, %1;" : "=r"(r) : "f"(x));
    return r;
}

__device__ __forceinline__ void mma_tf32(float& c0, float& c1, float& c2, float& c3,
                                         unsigned a0, unsigned a1, unsigned a2, unsigned a3,
                                         unsigned b0, unsigned b1) {
    asm volatile(
        "mma.sync.aligned.m16n8k8.row.col.f32.tf32.tf32.f32 "
        "{%0,%1,%2,%3}, {%4,%5,%6,%7}, {%8,%9}, {%0,%1,%2,%3};"
        : "+f"(c0), "+f"(c1), "+f"(c2), "+f"(c3)
        : "r"(a0), "r"(a1), "r"(a2), "r"(a3), "r"(b0), "r"(b1));
}

// =====================================================================
// SGEMM: C[M,N] = A[M,K] @ W[N,K]^T   (fp32, 128x128 block, 8x8/thread)
// =====================================================================
__global__ void __launch_bounds__(256) sgemm_nt(const float* __restrict__ A,
                                                const float* __restrict__ W,
                                                float* __restrict__ Cmat,
                                                int M, int N, int K) {
    __shared__ float As[8][132];
    __shared__ float Bs[8][132];

    const int tid = threadIdx.x;
    const int bm = blockIdx.y * 128;
    const int bn = blockIdx.x * 128;
    const int tr = tid >> 4;
    const int tc = tid & 15;
    const int lrow = tid >> 1;
    const int lcol = (tid & 1) * 4;

    const float* Ap = A + (size_t)(bm + lrow) * K + lcol;
    const float* Wp = W + (size_t)(bn + lrow) * K + lcol;

    float acc[8][8];
#pragma unroll
    for (int i = 0; i < 8; i++)
#pragma unroll
        for (int j = 0; j < 8; j++) acc[i][j] = 0.f;

    for (int k0 = 0; k0 < K; k0 += 8) {
        float4 a4 = *(const float4*)(Ap + k0);
        float4 b4 = *(const float4*)(Wp + k0);
        __syncthreads();
        As[lcol + 0][lrow] = a4.x; As[lcol + 1][lrow] = a4.y;
        As[lcol + 2][lrow] = a4.z; As[lcol + 3][lrow] = a4.w;
        Bs[lcol + 0][lrow] = b4.x; Bs[lcol + 1][lrow] = b4.y;
        Bs[lcol + 2][lrow] = b4.z; Bs[lcol + 3][lrow] = b4.w;
        __syncthreads();
#pragma unroll
        for (int kk = 0; kk < 8; kk++) {
            float ra[8], rb[8];
            *(float4*)(ra)     = *(const float4*)&As[kk][tr * 8];
            *(float4*)(ra + 4) = *(const float4*)&As[kk][tr * 8 + 4];
            *(float4*)(rb)     = *(const float4*)&Bs[kk][tc * 8];
            *(float4*)(rb + 4) = *(const float4*)&Bs[kk][tc * 8 + 4];
#pragma unroll
            for (int i = 0; i < 8; i++)
#pragma unroll
                for (int j = 0; j < 8; j++)
                    acc[i][j] += ra[i] * rb[j];
        }
    }

#pragma unroll
    for (int i = 0; i < 8; i++) {
        float* crow = Cmat + (size_t)(bm + tr * 8 + i) * N + bn + tc * 8;
#pragma unroll
        for (int j = 0; j < 8; j++) crow[j] = acc[i][j];
    }
}

// =====================================================================
// RoPE + split qkv[8192][1536] -> g_q/g_k/g_v in [bh][t][d] layout.
// =====================================================================
__global__ void __launch_bounds__(256) rope_split(const float* __restrict__ qkv,
                                                  const float* __restrict__ cosp,
                                                  const float* __restrict__ sinp,
                                                  float* __restrict__ q,
                                                  float* __restrict__ k,
                                                  float* __restrict__ v) {
    int idx = blockIdx.x * blockDim.x + threadIdx.x;   // 32*2048*32
    int d  = idx & 31;
    int t  = (idx >> 5) & (TT - 1);
    int bh = idx >> 16;
    int b = bh >> 3, h = bh & 7;

    size_t rowq = (size_t)(b * TT + t) * (3 * CC);
    int c = h * HD + d;
    float c1 = cosp[t * HD + d],      s1 = sinp[t * HD + d];
    float c2 = cosp[t * HD + d + 32], s2 = sinp[t * HD + d + 32];
    size_t dst = (size_t)(bh * TT + t) * HD + d;

    float x1 = qkv[rowq + c];
    float x2 = qkv[rowq + c + 32];
    q[dst]      = x1 * c1 - x2 * s1;
    q[dst + 32] = x2 * c2 + x1 * s2;

    x1 = qkv[rowq + CC + c];
    x2 = qkv[rowq + CC + c + 32];
    k[dst]      = x1 * c1 - x2 * s1;
    k[dst + 32] = x2 * c2 + x1 * s2;

    v[dst]      = qkv[rowq + 2 * CC + c];
    v[dst + 32] = qkv[rowq + 2 * CC + c + 32];
}

// =====================================================================
// Flash attention (causal) on tensor cores: mma.sync m16n8k8 tf32.
// Block: 128 threads / 4 warps. Q-tile 64 rows (16 per warp), K-tile 64.
// Q fragments live in registers; K/V staged in smem pre-converted to
// tf32; P converted C-layout -> A-layout with shuffles (no smem P).
// =====================================================================
__global__ void __launch_bounds__(128) attn_tc(const float* __restrict__ Q,
                                               const float* __restrict__ K,
                                               const float* __restrict__ V,
                                               float* __restrict__ Oatt) {
    __shared__ unsigned Ks[64][76];   // stride 76: (12g+q)%32 all-distinct for B-frag loads
    __shared__ unsigned Vs[64][72];   // stride 72: (8q+g)%32 all-distinct for B-frag loads

    const int tid  = threadIdx.x;
    const int warp = tid >> 5;
    const int lane = tid & 31;
    const int g    = lane >> 2;       // 0..7
    const int q    = lane & 3;        // 0..3
    const int qt   = (int)gridDim.x - 1 - (int)blockIdx.x;  // big tiles first
    const int q0   = qt * 64;
    const int bh   = blockIdx.y;
    const int row0 = q0 + warp * 16 + g;  // global q row of c0/c1
    const int row1 = row0 + 8;            // global q row of c2/c3

    // ---- Q fragments: scaled by 1/8 (softmax scale) and tf32-converted ----
    unsigned Qa[8][4];
    {
        const float* q0p = Q + ((size_t)bh * TT + row0) * HD;
        const float* q1p = Q + ((size_t)bh * TT + row1) * HD;
#pragma unroll
        for (int k = 0; k < 8; k++) {
            Qa[k][0] = f2tf32(0.125f * q0p[8 * k + q]);
            Qa[k][1] = f2tf32(0.125f * q1p[8 * k + q]);
            Qa[k][2] = f2tf32(0.125f * q0p[8 * k + q + 4]);
            Qa[k][3] = f2tf32(0.125f * q1p[8 * k + q + 4]);
        }
    }

    float Oac[8][4];
#pragma unroll
    for (int j = 0; j < 8; j++)
#pragma unroll
        for (int i = 0; i < 4; i++) Oac[j][i] = 0.f;
    float m0_ = -1e30f, m1_ = -1e30f, l0_ = 0.f, l1_ = 0.f;

    const int la = 4 * g + (q >> 1);   // shuffle source lanes for P layout conversion
    const int lb = la + 2;
    const bool odd = (q & 1);

    const int nkt = qt + 1;
    for (int kt = 0; kt < nkt; kt++) {
        const int k0 = kt * 64;
        __syncthreads();   // previous iteration's mma reads done
        {
            const float* kb = K + ((size_t)bh * TT + k0) * HD;
            const float* vb = V + ((size_t)bh * TT + k0) * HD;
#pragma unroll
            for (int i = 0; i < 8; i++) {
                int idx4 = tid + i * 128;          // 0..1023 float4s
                int row = idx4 >> 4, col = (idx4 & 15) * 4;
                float4 a = *(const float4*)(kb + row * HD + col);
                float4 b = *(const float4*)(vb + row * HD + col);
                *(uint4*)&Ks[row][col] = make_uint4(f2tf32(a.x), f2tf32(a.y),
                                                    f2tf32(a.z), f2tf32(a.w));
                *(uint4*)&Vs[row][col] = make_uint4(f2tf32(b.x), f2tf32(b.y),
                                                    f2tf32(b.z), f2tf32(b.w));
            }
        }
        __syncthreads();

        // ---- S = (Q/8) @ K^T ----
        float S[8][4];
#pragma unroll
        for (int j = 0; j < 8; j++)
#pragma unroll
            for (int i = 0; i < 4; i++) S[j][i] = 0.f;

#pragma unroll
        for (int k = 0; k < 8; k++) {
#pragma unroll
            for (int j = 0; j < 8; j++) {
                unsigned b0 = Ks[8 * j + g][8 * k + q];
                unsigned b1 = Ks[8 * j + g][8 * k + q + 4];
                mma_tf32(S[j][0], S[j][1], S[j][2], S[j][3],
                         Qa[k][0], Qa[k][1], Qa[k][2], Qa[k][3], b0, b1);
            }
        }

        // ---- causal mask (diagonal tile only) ----
        if (kt == nkt - 1) {
#pragma unroll
            for (int j = 0; j < 8; j++) {
                int c = k0 + 8 * j + 2 * q;
                if (c     > row0) S[j][0] = -1e30f;
                if (c + 1 > row0) S[j][1] = -1e30f;
                if (c     > row1) S[j][2] = -1e30f;
                if (c + 1 > row1) S[j][3] = -1e30f;
            }
        }

        // ---- online softmax ----
        float tm0 = -1e30f, tm1 = -1e30f;
#pragma unroll
        for (int j = 0; j < 8; j++) {
            tm0 = fmaxf(tm0, fmaxf(S[j][0], S[j][1]));
            tm1 = fmaxf(tm1, fmaxf(S[j][2], S[j][3]));
        }
        tm0 = fmaxf(tm0, __shfl_xor_sync(0xffffffffu, tm0, 1));
        tm0 = fmaxf(tm0, __shfl_xor_sync(0xffffffffu, tm0, 2));
        tm1 = fmaxf(tm1, __shfl_xor_sync(0xffffffffu, tm1, 1));
        tm1 = fmaxf(tm1, __shfl_xor_sync(0xffffffffu, tm1, 2));

        float nm0 = fmaxf(m0_, tm0), nm1 = fmaxf(m1_, tm1);
        float r0 = __expf(m0_ - nm0), r1 = __expf(m1_ - nm1);
        m0_ = nm0; m1_ = nm1;

        float rs0 = 0.f, rs1 = 0.f;
#pragma unroll
        for (int j = 0; j < 8; j++) {
            S[j][0] = __expf(S[j][0] - nm0);
            S[j][1] = __expf(S[j][1] - nm0);
            S[j][2] = __expf(S[j][2] - nm1);
            S[j][3] = __expf(S[j][3] - nm1);
            rs0 += S[j][0] + S[j][1];
            rs1 += S[j][2] + S[j][3];
        }
        rs0 += __shfl_xor_sync(0xffffffffu, rs0, 1);
        rs0 += __shfl_xor_sync(0xffffffffu, rs0, 2);
        rs1 += __shfl_xor_sync(0xffffffffu, rs1, 1);
        rs1 += __shfl_xor_sync(0xffffffffu, rs1, 2);
        l0_ = l0_ * r0 + rs0;
        l1_ = l1_ * r1 + rs1;

#pragma unroll
        for (int j = 0; j < 8; j++) {
            Oac[j][0] *= r0; Oac[j][1] *= r0;
            Oac[j][2] *= r1; Oac[j][3] *= r1;
        }

        // ---- O += P @ V  (P: C-frag -> A-frag via shuffles) ----
#pragma unroll
        for (int k = 0; k < 8; k++) {
            float w00 = __shfl_sync(0xffffffffu, S[k][0], la);
            float w01 = __shfl_sync(0xffffffffu, S[k][1], la);
            float w10 = __shfl_sync(0xffffffffu, S[k][0], lb);
            float w11 = __shfl_sync(0xffffffffu, S[k][1], lb);
            unsigned a0 = f2tf32(odd ? w01 : w00);
            unsigned a2 = f2tf32(odd ? w11 : w10);
            float x00 = __shfl_sync(0xffffffffu, S[k][2], la);
            float x01 = __shfl_sync(0xffffffffu, S[k][3], la);
            float x10 = __shfl_sync(0xffffffffu, S[k][2], lb);
            float x11 = __shfl_sync(0xffffffffu, S[k][3], lb);
            unsigned a1 = f2tf32(odd ? x01 : x00);
            unsigned a3 = f2tf32(odd ? x11 : x10);
#pragma unroll
            for (int j = 0; j < 8; j++) {
                unsigned b0 = Vs[8 * k + q][8 * j + g];
                unsigned b1 = Vs[8 * k + q + 4][8 * j + g];
                mma_tf32(Oac[j][0], Oac[j][1], Oac[j][2], Oac[j][3],
                         a0, a1, a2, a3, b0, b1);
            }
        }
    }

    // ---- epilogue: normalize and write [b][t][h*64+d] ----
    const int b = bh >> 3, h = bh & 7;
    float inv0 = 1.f / l0_, inv1 = 1.f / l1_;
    float* o0 = Oatt + ((size_t)(b * TT) + row0) * CC + h * HD;
    float* o1 = Oatt + ((size_t)(b * TT) + row1) * CC + h * HD;
#pragma unroll
    for (int j = 0; j < 8; j++) {
        float2 v0 = make_float2(Oac[j][0] * inv0, Oac[j][1] * inv0);
        float2 v1 = make_float2(Oac[j][2] * inv1, Oac[j][3] * inv1);
        *(float2*)&o0[8 * j + 2 * q] = v0;
        *(float2*)&o1[8 * j + 2 * q] = v1;
    }
}

// =====================================================================
extern "C" void kernel_launch(void* const* d_in, const int* in_sizes, int n_in,
                              void* d_out, int out_size) {
    const float* x    = (const float*)d_in[0];
    const float* cosp = (const float*)d_in[1];
    const float* sinp = (const float*)d_in[2];
    const float* Wqkv = (const float*)d_in[3];
    const float* Wout = (const float*)d_in[4];
    float* out = (float*)d_out;

    float *qkv, *q, *k, *v, *att;
    cudaGetSymbolAddress((void**)&qkv, g_qkv);
    cudaGetSymbolAddress((void**)&q,   g_q);
    cudaGetSymbolAddress((void**)&k,   g_k);
    cudaGetSymbolAddress((void**)&v,   g_v);
    cudaGetSymbolAddress((void**)&att, g_att);

    // 1) qkv = x @ Wqkv^T            [8192,512] x [1536,512]^T
    sgemm_nt<<<dim3((3 * CC) / 128, MM / 128), 256>>>(x, Wqkv, qkv, MM, 3 * CC, CC);
    // 2) RoPE + split into head-major q/k/v
    rope_split<<<(BH * TT * 32) / 256, 256>>>(qkv, cosp, sinp, q, k, v);
    // 3) causal flash attention on tensor cores
    attn_tc<<<dim3(TT / 64, BH), 128>>>(q, k, v, att);
    // 4) out = att @ Wout^T          [8192,512] x [512,512]^T
    sgemm_nt<<<dim3(CC / 128, MM / 128), 256>>>(att, Wout, out, MM, CC, CC);
}

// round 4
// speedup vs baseline: 4.0016x; 1.4932x over previous
#include <cuda_runtime.h>
#include <cstdint>
#include <math.h>

// Problem constants
#define BB 4
#define TT 2048
#define CC 512
#define HH 8
#define HD 64
#define MM (BB*TT)          // 8192
#define BH (BB*HH)          // 32

// ---------------- device scratch ----------------
__device__ float g_qkv[MM * 3 * CC];
__device__ float g_q[BH * TT * HD];
__device__ float g_k[BH * TT * HD];
__device__ float g_v[BH * TT * HD];
__device__ float g_att[MM * CC];

// ---------------- tf32 helpers ----------------
__device__ __forceinline__ unsigned f2tf32(float x) {
    unsigned r;
    asm("cvt.rna.tf32.f32 %0, %1;" : "=r"(r) : "f"(x));
    return r;
}

__device__ __forceinline__ void mma_tf32(float& c0, float& c1, float& c2, float& c3,
                                         unsigned a0, unsigned a1, unsigned a2, unsigned a3,
                                         unsigned b0, unsigned b1) {
    asm volatile(
        "mma.sync.aligned.m16n8k8.row.col.f32.tf32.tf32.f32 "
        "{%0,%1,%2,%3}, {%4,%5,%6,%7}, {%8,%9}, {%0,%1,%2,%3};"
        : "+f"(c0), "+f"(c1), "+f"(c2), "+f"(c3)
        : "r"(a0), "r"(a1), "r"(a2), "r"(a3), "r"(b0), "r"(b1));
}

// =====================================================================
// TF32 tensor-core GEMM: C[M,N] = A[M,K] @ W[N,K]^T
// 128x128 block, 8 warps (warp tile 64x32), BK=16.
// Smem staged as [k][m] / [k][n] with stride 136 -> fragment LDS
// addresses are (8q+g) mod 32: all 32 banks, conflict-free.
// =====================================================================
__global__ void __launch_bounds__(256) gemm_tf32_nt(const float* __restrict__ A,
                                                    const float* __restrict__ W,
                                                    float* __restrict__ Cmat,
                                                    int M, int N, int K) {
    __shared__ unsigned As[16][136];
    __shared__ unsigned Ws[16][136];

    const int tid  = threadIdx.x;
    const int warp = tid >> 5;
    const int lane = tid & 31;
    const int g    = lane >> 2;       // 0..7
    const int q    = lane & 3;        // 0..3
    const int bm = blockIdx.y * 128;
    const int bn = blockIdx.x * 128;
    const int wm = (warp & 1) * 64;   // warp m offset in tile
    const int wn = (warp >> 1) * 32;  // warp n offset in tile

    // global-load assignment: thread -> (row lm, k-offset lk), 2 float4 each
    const int lm = tid & 127;
    const int lk = (tid >> 7) * 8;    // 0 or 8

    const float* Ap = A + (size_t)(bm + lm) * K + lk;
    const float* Wp = W + (size_t)(bn + lm) * K + lk;

    float acc[4][4][4];
#pragma unroll
    for (int mi = 0; mi < 4; mi++)
#pragma unroll
        for (int ni = 0; ni < 4; ni++)
#pragma unroll
            for (int c = 0; c < 4; c++) acc[mi][ni][c] = 0.f;

    for (int k0 = 0; k0 < K; k0 += 16) {
        float4 a1 = *(const float4*)(Ap + k0);
        float4 a2 = *(const float4*)(Ap + k0 + 4);
        float4 w1 = *(const float4*)(Wp + k0);
        float4 w2 = *(const float4*)(Wp + k0 + 4);
        __syncthreads();
        As[lk + 0][lm] = f2tf32(a1.x); As[lk + 1][lm] = f2tf32(a1.y);
        As[lk + 2][lm] = f2tf32(a1.z); As[lk + 3][lm] = f2tf32(a1.w);
        As[lk + 4][lm] = f2tf32(a2.x); As[lk + 5][lm] = f2tf32(a2.y);
        As[lk + 6][lm] = f2tf32(a2.z); As[lk + 7][lm] = f2tf32(a2.w);
        Ws[lk + 0][lm] = f2tf32(w1.x); Ws[lk + 1][lm] = f2tf32(w1.y);
        Ws[lk + 2][lm] = f2tf32(w1.z); Ws[lk + 3][lm] = f2tf32(w1.w);
        Ws[lk + 4][lm] = f2tf32(w2.x); Ws[lk + 5][lm] = f2tf32(w2.y);
        Ws[lk + 6][lm] = f2tf32(w2.z); Ws[lk + 7][lm] = f2tf32(w2.w);
        __syncthreads();

#pragma unroll
        for (int ks = 0; ks < 2; ks++) {
            const int kk = ks * 8;
            unsigned af[4][4];
#pragma unroll
            for (int mi = 0; mi < 4; mi++) {
                const int m = wm + mi * 16;
                af[mi][0] = As[kk + q][m + g];
                af[mi][1] = As[kk + q][m + g + 8];
                af[mi][2] = As[kk + q + 4][m + g];
                af[mi][3] = As[kk + q + 4][m + g + 8];
            }
            unsigned bf[4][2];
#pragma unroll
            for (int ni = 0; ni < 4; ni++) {
                const int n = wn + ni * 8;
                bf[ni][0] = Ws[kk + q][n + g];
                bf[ni][1] = Ws[kk + q + 4][n + g];
            }
#pragma unroll
            for (int mi = 0; mi < 4; mi++)
#pragma unroll
                for (int ni = 0; ni < 4; ni++)
                    mma_tf32(acc[mi][ni][0], acc[mi][ni][1], acc[mi][ni][2], acc[mi][ni][3],
                             af[mi][0], af[mi][1], af[mi][2], af[mi][3],
                             bf[ni][0], bf[ni][1]);
        }
    }

    // epilogue
#pragma unroll
    for (int mi = 0; mi < 4; mi++) {
#pragma unroll
        for (int ni = 0; ni < 4; ni++) {
            const int m = bm + wm + mi * 16 + g;
            const int n = bn + wn + ni * 8 + 2 * q;
            *(float2*)&Cmat[(size_t)m * N + n] =
                make_float2(acc[mi][ni][0], acc[mi][ni][1]);
            *(float2*)&Cmat[(size_t)(m + 8) * N + n] =
                make_float2(acc[mi][ni][2], acc[mi][ni][3]);
        }
    }
}

// =====================================================================
// RoPE + split qkv[8192][1536] -> g_q/g_k/g_v in [bh][t][d] layout.
// =====================================================================
__global__ void __launch_bounds__(256) rope_split(const float* __restrict__ qkv,
                                                  const float* __restrict__ cosp,
                                                  const float* __restrict__ sinp,
                                                  float* __restrict__ q,
                                                  float* __restrict__ k,
                                                  float* __restrict__ v) {
    int idx = blockIdx.x * blockDim.x + threadIdx.x;   // 32*2048*32
    int d  = idx & 31;
    int t  = (idx >> 5) & (TT - 1);
    int bh = idx >> 16;
    int b = bh >> 3, h = bh & 7;

    size_t rowq = (size_t)(b * TT + t) * (3 * CC);
    int c = h * HD + d;
    float c1 = cosp[t * HD + d],      s1 = sinp[t * HD + d];
    float c2 = cosp[t * HD + d + 32], s2 = sinp[t * HD + d + 32];
    size_t dst = (size_t)(bh * TT + t) * HD + d;

    float x1 = qkv[rowq + c];
    float x2 = qkv[rowq + c + 32];
    q[dst]      = x1 * c1 - x2 * s1;
    q[dst + 32] = x2 * c2 + x1 * s2;

    x1 = qkv[rowq + CC + c];
    x2 = qkv[rowq + CC + c + 32];
    k[dst]      = x1 * c1 - x2 * s1;
    k[dst + 32] = x2 * c2 + x1 * s2;

    v[dst]      = qkv[rowq + 2 * CC + c];
    v[dst + 32] = qkv[rowq + 2 * CC + c + 32];
}

// =====================================================================
// Flash attention (causal) on tensor cores: mma.sync m16n8k8 tf32.
// (Round-2 version: passed at rel_err 3.1e-4)
// =====================================================================
__global__ void __launch_bounds__(128) attn_tc(const float* __restrict__ Q,
                                               const float* __restrict__ K,
                                               const float* __restrict__ V,
                                               float* __restrict__ Oatt) {
    __shared__ unsigned Ks[64][76];   // stride 76: (12g+q)%32 all-distinct
    __shared__ unsigned Vs[64][72];   // stride 72: (8q+g)%32 all-distinct

    const int tid  = threadIdx.x;
    const int warp = tid >> 5;
    const int lane = tid & 31;
    const int g    = lane >> 2;
    const int q    = lane & 3;
    const int qt   = (int)gridDim.x - 1 - (int)blockIdx.x;  // big tiles first
    const int q0   = qt * 64;
    const int bh   = blockIdx.y;
    const int row0 = q0 + warp * 16 + g;
    const int row1 = row0 + 8;

    unsigned Qa[8][4];
    {
        const float* q0p = Q + ((size_t)bh * TT + row0) * HD;
        const float* q1p = Q + ((size_t)bh * TT + row1) * HD;
#pragma unroll
        for (int k = 0; k < 8; k++) {
            Qa[k][0] = f2tf32(0.125f * q0p[8 * k + q]);
            Qa[k][1] = f2tf32(0.125f * q1p[8 * k + q]);
            Qa[k][2] = f2tf32(0.125f * q0p[8 * k + q + 4]);
            Qa[k][3] = f2tf32(0.125f * q1p[8 * k + q + 4]);
        }
    }

    float Oac[8][4];
#pragma unroll
    for (int j = 0; j < 8; j++)
#pragma unroll
        for (int i = 0; i < 4; i++) Oac[j][i] = 0.f;
    float m0_ = -1e30f, m1_ = -1e30f, l0_ = 0.f, l1_ = 0.f;

    const int la = 4 * g + (q >> 1);
    const int lb = la + 2;
    const bool odd = (q & 1);

    const int nkt = qt + 1;
    for (int kt = 0; kt < nkt; kt++) {
        const int k0 = kt * 64;
        __syncthreads();
        {
            const float* kb = K + ((size_t)bh * TT + k0) * HD;
            const float* vb = V + ((size_t)bh * TT + k0) * HD;
#pragma unroll
            for (int i = 0; i < 8; i++) {
                int idx4 = tid + i * 128;
                int row = idx4 >> 4, col = (idx4 & 15) * 4;
                float4 a = *(const float4*)(kb + row * HD + col);
                float4 b = *(const float4*)(vb + row * HD + col);
                *(uint4*)&Ks[row][col] = make_uint4(f2tf32(a.x), f2tf32(a.y),
                                                    f2tf32(a.z), f2tf32(a.w));
                *(uint4*)&Vs[row][col] = make_uint4(f2tf32(b.x), f2tf32(b.y),
                                                    f2tf32(b.z), f2tf32(b.w));
            }
        }
        __syncthreads();

        float S[8][4];
#pragma unroll
        for (int j = 0; j < 8; j++)
#pragma unroll
            for (int i = 0; i < 4; i++) S[j][i] = 0.f;

#pragma unroll
        for (int k = 0; k < 8; k++) {
#pragma unroll
            for (int j = 0; j < 8; j++) {
                unsigned b0 = Ks[8 * j + g][8 * k + q];
                unsigned b1 = Ks[8 * j + g][8 * k + q + 4];
                mma_tf32(S[j][0], S[j][1], S[j][2], S[j][3],
                         Qa[k][0], Qa[k][1], Qa[k][2], Qa[k][3], b0, b1);
            }
        }

        if (kt == nkt - 1) {
#pragma unroll
            for (int j = 0; j < 8; j++) {
                int c = k0 + 8 * j + 2 * q;
                if (c     > row0) S[j][0] = -1e30f;
                if (c + 1 > row0) S[j][1] = -1e30f;
                if (c     > row1) S[j][2] = -1e30f;
                if (c + 1 > row1) S[j][3] = -1e30f;
            }
        }

        float tm0 = -1e30f, tm1 = -1e30f;
#pragma unroll
        for (int j = 0; j < 8; j++) {
            tm0 = fmaxf(tm0, fmaxf(S[j][0], S[j][1]));
            tm1 = fmaxf(tm1, fmaxf(S[j][2], S[j][3]));
        }
        tm0 = fmaxf(tm0, __shfl_xor_sync(0xffffffffu, tm0, 1));
        tm0 = fmaxf(tm0, __shfl_xor_sync(0xffffffffu, tm0, 2));
        tm1 = fmaxf(tm1, __shfl_xor_sync(0xffffffffu, tm1, 1));
        tm1 = fmaxf(tm1, __shfl_xor_sync(0xffffffffu, tm1, 2));

        float nm0 = fmaxf(m0_, tm0), nm1 = fmaxf(m1_, tm1);
        float r0 = __expf(m0_ - nm0), r1 = __expf(m1_ - nm1);
        m0_ = nm0; m1_ = nm1;

        float rs0 = 0.f, rs1 = 0.f;
#pragma unroll
        for (int j = 0; j < 8; j++) {
            S[j][0] = __expf(S[j][0] - nm0);
            S[j][1] = __expf(S[j][1] - nm0);
            S[j][2] = __expf(S[j][2] - nm1);
            S[j][3] = __expf(S[j][3] - nm1);
            rs0 += S[j][0] + S[j][1];
            rs1 += S[j][2] + S[j][3];
        }
        rs0 += __shfl_xor_sync(0xffffffffu, rs0, 1);
        rs0 += __shfl_xor_sync(0xffffffffu, rs0, 2);
        rs1 += __shfl_xor_sync(0xffffffffu, rs1, 1);
        rs1 += __shfl_xor_sync(0xffffffffu, rs1, 2);
        l0_ = l0_ * r0 + rs0;
        l1_ = l1_ * r1 + rs1;

#pragma unroll
        for (int j = 0; j < 8; j++) {
            Oac[j][0] *= r0; Oac[j][1] *= r0;
            Oac[j][2] *= r1; Oac[j][3] *= r1;
        }

#pragma unroll
        for (int k = 0; k < 8; k++) {
            float w00 = __shfl_sync(0xffffffffu, S[k][0], la);
            float w01 = __shfl_sync(0xffffffffu, S[k][1], la);
            float w10 = __shfl_sync(0xffffffffu, S[k][0], lb);
            float w11 = __shfl_sync(0xffffffffu, S[k][1], lb);
            unsigned a0 = f2tf32(odd ? w01 : w00);
            unsigned a2 = f2tf32(odd ? w11 : w10);
            float x00 = __shfl_sync(0xffffffffu, S[k][2], la);
            float x01 = __shfl_sync(0xffffffffu, S[k][3], la);
            float x10 = __shfl_sync(0xffffffffu, S[k][2], lb);
            float x11 = __shfl_sync(0xffffffffu, S[k][3], lb);
            unsigned a1 = f2tf32(odd ? x01 : x00);
            unsigned a3 = f2tf32(odd ? x11 : x10);
#pragma unroll
            for (int j = 0; j < 8; j++) {
                unsigned b0 = Vs[8 * k + q][8 * j + g];
                unsigned b1 = Vs[8 * k + q + 4][8 * j + g];
                mma_tf32(Oac[j][0], Oac[j][1], Oac[j][2], Oac[j][3],
                         a0, a1, a2, a3, b0, b1);
            }
        }
    }

    const int b = bh >> 3, h = bh & 7;
    float inv0 = 1.f / l0_, inv1 = 1.f / l1_;
    float* o0 = Oatt + ((size_t)(b * TT) + row0) * CC + h * HD;
    float* o1 = Oatt + ((size_t)(b * TT) + row1) * CC + h * HD;
#pragma unroll
    for (int j = 0; j < 8; j++) {
        float2 v0 = make_float2(Oac[j][0] * inv0, Oac[j][1] * inv0);
        float2 v1 = make_float2(Oac[j][2] * inv1, Oac[j][3] * inv1);
        *(float2*)&o0[8 * j + 2 * q] = v0;
        *(float2*)&o1[8 * j + 2 * q] = v1;
    }
}

// =====================================================================
extern "C" void kernel_launch(void* const* d_in, const int* in_sizes, int n_in,
                              void* d_out, int out_size) {
    const float* x    = (const float*)d_in[0];
    const float* cosp = (const float*)d_in[1];
    const float* sinp = (const float*)d_in[2];
    const float* Wqkv = (const float*)d_in[3];
    const float* Wout = (const float*)d_in[4];
    float* out = (float*)d_out;

    float *qkv, *q, *k, *v, *att;
    cudaGetSymbolAddress((void**)&qkv, g_qkv);
    cudaGetSymbolAddress((void**)&q,   g_q);
    cudaGetSymbolAddress((void**)&k,   g_k);
    cudaGetSymbolAddress((void**)&v,   g_v);
    cudaGetSymbolAddress((void**)&att, g_att);

    // 1) qkv = x @ Wqkv^T            [8192,512] x [1536,512]^T  (tf32 TC)
    gemm_tf32_nt<<<dim3((3 * CC) / 128, MM / 128), 256>>>(x, Wqkv, qkv, MM, 3 * CC, CC);
    // 2) RoPE + split into head-major q/k/v
    rope_split<<<(BH * TT * 32) / 256, 256>>>(qkv, cosp, sinp, q, k, v);
    // 3) causal flash attention on tensor cores
    attn_tc<<<dim3(TT / 64, BH), 128>>>(q, k, v, att);
    // 4) out = att @ Wout^T          [8192,512] x [512,512]^T   (tf32 TC)
    gemm_tf32_nt<<<dim3(CC / 128, MM / 128), 256>>>(att, Wout, out, MM, CC, CC);
}